// round 5
// baseline (speedup 1.0000x reference)
#include <cuda_runtime.h>
#include <cstdint>

#define C_IN   128
#define C_OUT  256
#define TAPS   4
#define N_MAX  262144
#define PADN_MAX (N_MAX + TAPS * 128)
#define BN_EPS 1e-4f
#define PIT    36                  // smem pitch in floats (conflict-free)
#define ASTAGE (128 * PIT)         // floats per stage (A or B chunk)

// ---------------- device scratch ----------------
__device__ float g_scratch[(size_t)PADN_MAX * C_OUT];   // rows for multi-contributor sites only
__device__ int   g_pslot[N_MAX * TAPS];                 // pslot[site*4+tap] = perm position or -1
__device__ int   g_perm[PADN_MAX];                      // perm position -> input row
__device__ int   g_psite[PADN_MAX];                     // perm position -> output site (-1 = pad)
__device__ int   g_cntSite[N_MAX];                      // contributors per site
__device__ float g_Bt[TAPS * C_OUT * C_IN];             // W as [tap][n][k], tf32-rounded
__device__ int   g_tap_count[TAPS];
__device__ int   g_pad_base[TAPS + 1];
__device__ int   g_tap_cursor[TAPS];
__device__ float g_sum[C_OUT];
__device__ float g_sumsq[C_OUT];
__device__ float g_cnt;
__device__ float g_scale[C_OUT];
__device__ float g_bias[C_OUT];

// ---------------- helpers ----------------
__device__ __forceinline__ uint32_t smem_u32(const void* p) {
    uint32_t a;
    asm("{ .reg .u64 t; cvta.to.shared.u64 t, %1; cvt.u32.u64 %0, t; }" : "=r"(a) : "l"(p));
    return a;
}
__device__ __forceinline__ uint32_t f2tf32(float f) {
    uint32_t r;
    asm("cvt.rna.tf32.f32 %0, %1;" : "=r"(r) : "f"(f));
    return r;
}

#define CP_ASYNC(sa, ga, sz) \
    asm volatile("cp.async.cg.shared.global [%0], [%1], 16, %2;" :: "r"(sa), "l"(ga), "r"(sz))
#define CP_COMMIT() asm volatile("cp.async.commit_group;")
#define CP_WAIT(n)  asm volatile("cp.async.wait_group %0;" :: "n"(n))

#define MMA(d, a, b0, b1)                                                          \
    asm volatile("mma.sync.aligned.m16n8k8.row.col.f32.tf32.tf32.f32 "             \
                 "{%0,%1,%2,%3}, {%4,%5,%6,%7}, {%8,%9}, {%0,%1,%2,%3};"           \
                 : "+f"((d)[0]), "+f"((d)[1]), "+f"((d)[2]), "+f"((d)[3])          \
                 : "r"((a)[0]), "r"((a)[1]), "r"((a)[2]), "r"((a)[3]),             \
                   "r"(b0), "r"(b1))

// ---------------- K_prep: W transpose+round, tap histogram, psite init ----------------
__global__ void k_prep(const float* __restrict__ W, const int* __restrict__ offset, int N) {
    for (int i = blockIdx.x * blockDim.x + threadIdx.x; i < TAPS * C_IN * C_OUT;
         i += gridDim.x * blockDim.x) {
        int t = i / (C_IN * C_OUT);
        int r = i % (C_IN * C_OUT);
        int k = r >> 8, n = r & 255;
        g_Bt[t * C_OUT * C_IN + n * C_IN + k] = __uint_as_float(f2tf32(W[i]));
    }
    for (int i = blockIdx.x * blockDim.x + threadIdx.x; i < PADN_MAX;
         i += gridDim.x * blockDim.x)
        g_psite[i] = -1;
    int c0 = 0, c1 = 0, c2 = 0, c3 = 0;
    for (int i = blockIdx.x * blockDim.x + threadIdx.x; i < N;
         i += gridDim.x * blockDim.x) {
        int k = offset[i];
        c0 += (k == 0); c1 += (k == 1); c2 += (k == 2); c3 += (k == 3);
    }
    c0 = __reduce_add_sync(0xffffffffu, c0);
    c1 = __reduce_add_sync(0xffffffffu, c1);
    c2 = __reduce_add_sync(0xffffffffu, c2);
    c3 = __reduce_add_sync(0xffffffffu, c3);
    if ((threadIdx.x & 31) == 0) {
        atomicAdd(&g_tap_count[0], c0);
        atomicAdd(&g_tap_count[1], c1);
        atomicAdd(&g_tap_count[2], c2);
        atomicAdd(&g_tap_count[3], c3);
    }
}

// ---------------- K_prefix ----------------
__global__ void k_prefix() {
    if (threadIdx.x == 0 && blockIdx.x == 0) {
        int b = 0;
        for (int t = 0; t < TAPS; t++) {
            g_pad_base[t]   = b;
            g_tap_cursor[t] = b;
            b += (g_tap_count[t] + 127) & ~127;
        }
        g_pad_base[TAPS] = b;
    }
}

// ---------------- K_perm: permutation + inverse maps + per-site counts ----------------
__global__ void k_perm(const int* __restrict__ offset, const int* __restrict__ out_index,
                       const float* __restrict__ mask, int N) {
    int lane = threadIdx.x & 31;
    float cm = 0.f;
    for (int i = blockIdx.x * blockDim.x + threadIdx.x; i < N;
         i += gridDim.x * blockDim.x) {
        int k = offset[i];
        unsigned grp = __match_any_sync(0xffffffffu, k);
        int leader   = __ffs(grp) - 1;
        int rank     = __popc(grp & ((1u << lane) - 1u));
        int base = 0;
        if (lane == leader) base = atomicAdd(&g_tap_cursor[k], __popc(grp));
        base = __shfl_sync(0xffffffffu, base, leader);
        int pos  = base + rank;
        int site = out_index[i];
        g_perm[pos] = i;
        g_psite[pos] = site;
        g_pslot[(size_t)site * TAPS + k] = pos;
        atomicAdd(&g_cntSite[site], 1);
        cm += mask[i];
    }
#pragma unroll
    for (int o = 16; o; o >>= 1) cm += __shfl_xor_sync(0xffffffffu, cm, o);
    if ((threadIdx.x & 31) == 0) atomicAdd(&g_cnt, cm);
}

// ---------------- K_conv: per-tap tf32 GEMM, routed stores + fused linear stats ----------------
// 1D grid: tile = tileOff + (bid>>1), col = (bid&1)*128  (adjacent bids reuse A tile in L2)
#define SMEM_BYTES ((128 * 4 + 4 * ASTAGE) * 4)

__global__ __launch_bounds__(256, 2)
void k_conv(const float* __restrict__ x, float* __restrict__ y, int tileOff) {
    extern __shared__ float sm[];
    int*   srow  = (int*)sm;                 // 128: input row per perm pos
    int*   sdst  = (int*)sm + 128;           // 128: dest row index (site or pos), -1 = pad
    int*   sIsY  = (int*)sm + 256;           // 128: 1 -> write y, 0 -> write scratch
    float* sflag = sm + 384;                 // 128: 1.0 valid row, 0.0 pad
    float* As    = sm + 512;                 // 2 stages of 128 x PIT
    float* Bs    = sm + 512 + 2 * ASTAGE;

    const int tid  = threadIdx.x;
    const int lane = tid & 31;
    const int wid  = tid >> 5;
    const int wm   = wid & 3;
    const int wn   = wid >> 2;
    const int p0   = (tileOff + ((int)blockIdx.x >> 1)) * 128;
    if (p0 >= g_pad_base[TAPS]) return;

    int tap = 0;
#pragma unroll
    for (int t = 1; t < TAPS; t++)
        if (p0 >= g_pad_base[t]) tap = t;

    const int colStart = ((int)blockIdx.x & 1) * 128;
    const float* Bt = g_Bt + (size_t)tap * (C_OUT * C_IN);

    if (tid < 128) {
        int pos  = p0 + tid;
        int site = g_psite[pos];
        srow[tid]  = g_perm[pos];            // stale for pads; in-bounds, unused downstream
        sflag[tid] = (site >= 0) ? 1.f : 0.f;
        int cnt = (site >= 0) ? g_cntSite[site] : 0;
        sIsY[tid] = (cnt == 1);
        sdst[tid] = (site < 0) ? -1 : ((cnt == 1) ? site : pos);
    }
    __syncthreads();

    const uint32_t aBase = smem_u32(As);
    const uint32_t bBase = smem_u32(Bs);

    float acc[2][8][4];
#pragma unroll
    for (int i = 0; i < 2; i++)
#pragma unroll
        for (int j = 0; j < 8; j++)
#pragma unroll
            for (int q = 0; q < 4; q++) acc[i][j][q] = 0.f;

#define LOAD_CHUNK(c)                                                              \
    do {                                                                           \
        int _k0 = (c) * 32, _st = (c) & 1;                                         \
        uint32_t _sa = aBase + (uint32_t)(_st * ASTAGE) * 4u;                      \
        uint32_t _sb = bBase + (uint32_t)(_st * ASTAGE) * 4u;                      \
        _Pragma("unroll")                                                          \
        for (int _u = 0; _u < 4; _u++) {                                           \
            int _seg = _u * 256 + tid;                                             \
            int _row = _seg >> 3, _q = _seg & 7;                                   \
            int _src = srow[_row];                                                 \
            const float* _ga = x + (size_t)_src * C_IN + _k0 + _q * 4;             \
            CP_ASYNC(_sa + (uint32_t)(_row * PIT + _q * 4) * 4u, _ga, 16);         \
        }                                                                          \
        _Pragma("unroll")                                                          \
        for (int _u = 0; _u < 4; _u++) {                                           \
            int _seg = _u * 256 + tid;                                             \
            int _n = _seg >> 3, _q = _seg & 7;                                     \
            const float* _gb = Bt + (size_t)(colStart + _n) * C_IN + _k0 + _q * 4; \
            CP_ASYNC(_sb + (uint32_t)(_n * PIT + _q * 4) * 4u, _gb, 16);           \
        }                                                                          \
        CP_COMMIT();                                                               \
    } while (0)

    LOAD_CHUNK(0);
    for (int c = 0; c < 4; c++) {
        if (c < 3) {
            LOAD_CHUNK(c + 1);
            CP_WAIT(1);
        } else {
            CP_WAIT(0);
        }
        __syncthreads();

        const float* Ac = As + (c & 1) * ASTAGE;
        const float* Bc = Bs + (c & 1) * ASTAGE;

#pragma unroll
        for (int kk = 0; kk < 4; kk++) {
            const int k8 = kk * 8;
            uint32_t a[2][4];
#pragma unroll
            for (int i = 0; i < 2; i++) {
                const float* ap = Ac + (wm * 32 + i * 16 + (lane >> 2)) * PIT + k8 + (lane & 3);
                a[i][0] = f2tf32(ap[0]);
                a[i][1] = f2tf32(ap[8 * PIT]);
                a[i][2] = f2tf32(ap[4]);
                a[i][3] = f2tf32(ap[8 * PIT + 4]);
            }
#pragma unroll
            for (int j = 0; j < 8; j++) {
                const float* bp = Bc + (wn * 64 + j * 8 + (lane >> 2)) * PIT + k8 + (lane & 3);
                uint32_t b0 = __float_as_uint(bp[0]);
                uint32_t b1 = __float_as_uint(bp[4]);
                MMA(acc[0][j], a[0], b0, b1);
                MMA(acc[1][j], a[1], b0, b1);
            }
        }
        __syncthreads();
    }

    // ---- epilogue: routed stores (y for single-contributor sites, scratch otherwise) ----
#pragma unroll
    for (int i = 0; i < 2; i++) {
        const int lr = wm * 32 + i * 16 + (lane >> 2);
#pragma unroll
        for (int j = 0; j < 8; j++) {
            int cg = colStart + wn * 64 + j * 8 + (lane & 3) * 2;
            int d0 = sdst[lr];
            if (d0 >= 0) {
                float* o = (sIsY[lr] ? y : g_scratch) + (size_t)d0 * C_OUT + cg;
                *(float2*)o = make_float2(acc[i][j][0], acc[i][j][1]);
            }
            int d1 = sdst[lr + 8];
            if (d1 >= 0) {
                float* o = (sIsY[lr + 8] ? y : g_scratch) + (size_t)d1 * C_OUT + cg;
                *(float2*)o = make_float2(acc[i][j][2], acc[i][j][3]);
            }
        }
    }

    // ---- fused linear stats: sum(contrib) and sum(contrib^2), pad rows masked ----
#pragma unroll
    for (int j = 0; j < 8; j++) {
        float se = 0.f, so = 0.f, qe = 0.f, qo = 0.f;
#pragma unroll
        for (int i = 0; i < 2; i++) {
            const int lr = wm * 32 + i * 16 + (lane >> 2);
            float f0 = sflag[lr], f1 = sflag[lr + 8];
            se += f0 * acc[i][j][0] + f1 * acc[i][j][2];
            so += f0 * acc[i][j][1] + f1 * acc[i][j][3];
            qe += f0 * acc[i][j][0] * acc[i][j][0] + f1 * acc[i][j][2] * acc[i][j][2];
            qo += f0 * acc[i][j][1] * acc[i][j][1] + f1 * acc[i][j][3] * acc[i][j][3];
        }
#pragma unroll
        for (int o = 4; o <= 16; o <<= 1) {
            se += __shfl_xor_sync(0xffffffffu, se, o);
            so += __shfl_xor_sync(0xffffffffu, so, o);
            qe += __shfl_xor_sync(0xffffffffu, qe, o);
            qo += __shfl_xor_sync(0xffffffffu, qo, o);
        }
        if (lane < 4) {
            int col = colStart + wn * 64 + j * 8 + lane * 2;
            atomicAdd(&g_sum[col], se);
            atomicAdd(&g_sum[col + 1], so);
            atomicAdd(&g_sumsq[col], qe);
            atomicAdd(&g_sumsq[col + 1], qo);
        }
    }
#undef LOAD_CHUNK
}

// ---------------- K_combine: multi-contributor sites only ----------------
// 512 sites/block; warp group g handles one site at a time, lane = 8 channels.
__global__ __launch_bounds__(256)
void k_combine(float* __restrict__ y, int N) {
    __shared__ float ssq[C_OUT];
    const int tid  = threadIdx.x;
    const int lane = tid & 31;
    const int g    = tid >> 5;
    const int s0   = blockIdx.x * 512;

    ssq[tid] = 0.f;
    __syncthreads();

    for (int it = 0; it < 64; it++) {
        int site = s0 + it * 8 + g;
        if (site >= N) continue;
        if (g_cntSite[site] < 2) continue;
        float v[8] = {0, 0, 0, 0, 0, 0, 0, 0};
        float q[8] = {0, 0, 0, 0, 0, 0, 0, 0};
#pragma unroll
        for (int t = 0; t < TAPS; t++) {
            int p = g_pslot[(size_t)site * TAPS + t];
            if (p < 0) continue;
            const float4* row = (const float4*)(g_scratch + (size_t)p * C_OUT + lane * 8);
            float4 a = row[0], b = row[1];
            v[0] += a.x; v[1] += a.y; v[2] += a.z; v[3] += a.w;
            v[4] += b.x; v[5] += b.y; v[6] += b.z; v[7] += b.w;
            q[0] += a.x * a.x; q[1] += a.y * a.y; q[2] += a.z * a.z; q[3] += a.w * a.w;
            q[4] += b.x * b.x; q[5] += b.y * b.y; q[6] += b.z * b.z; q[7] += b.w * b.w;
        }
        float4* o = (float4*)(y + (size_t)site * C_OUT + lane * 8);
        o[0] = make_float4(v[0], v[1], v[2], v[3]);
        o[1] = make_float4(v[4], v[5], v[6], v[7]);
#pragma unroll
        for (int c = 0; c < 8; c++)
            atomicAdd(&ssq[lane * 8 + c], v[c] * v[c] - q[c]);
    }
    __syncthreads();
    atomicAdd(&g_sumsq[tid], ssq[tid]);
}

// ---------------- K_bn ----------------
__global__ void k_bn(const float* __restrict__ gamma, const float* __restrict__ beta) {
    int c = threadIdx.x;
    float cnt  = g_cnt;
    float mean = g_sum[c] / cnt;
    float var  = fmaxf(g_sumsq[c] / cnt - mean * mean, 0.f);
    float sc   = rsqrtf(var + BN_EPS) * gamma[c];
    float bi   = beta[c] - mean * sc;
    g_scale[c] = sc;
    g_bias[c]  = bi;
    g_sum[c]   = 0.f;
    g_sumsq[c] = 0.f;
    if (c == 0) g_cnt = 0.f;
    if (c < TAPS) g_tap_count[c] = 0;
}

// ---------------- K_final: normalize in place (skip-read empty rows) ----------------
__global__ __launch_bounds__(256)
void k_final(float* __restrict__ y, const float* __restrict__ mask, int N) {
    const int tid  = threadIdx.x;
    const int lane = tid & 31;
    const int g    = tid >> 5;
    const int s0   = blockIdx.x * 512;

    const float4 sc0 = *(const float4*)&g_scale[lane * 8];
    const float4 sc1 = *(const float4*)&g_scale[lane * 8 + 4];
    const float4 bi0 = *(const float4*)&g_bias[lane * 8];
    const float4 bi1 = *(const float4*)&g_bias[lane * 8 + 4];

    for (int it = 0; it < 64; it++) {
        int site = s0 + it * 8 + g;
        if (site >= N) continue;
        float4* o = (float4*)(y + (size_t)site * C_OUT + lane * 8);
        float4 v0 = make_float4(0.f, 0.f, 0.f, 0.f), v1 = v0;
        if (g_cntSite[site] > 0) {
            float m = mask[site];
            float4 a = o[0], b = o[1];
            v0.x = fmaxf(fmaf(a.x, sc0.x, bi0.x), 0.f) * m;
            v0.y = fmaxf(fmaf(a.y, sc0.y, bi0.y), 0.f) * m;
            v0.z = fmaxf(fmaf(a.z, sc0.z, bi0.z), 0.f) * m;
            v0.w = fmaxf(fmaf(a.w, sc0.w, bi0.w), 0.f) * m;
            v1.x = fmaxf(fmaf(b.x, sc1.x, bi1.x), 0.f) * m;
            v1.y = fmaxf(fmaf(b.y, sc1.y, bi1.y), 0.f) * m;
            v1.z = fmaxf(fmaf(b.z, sc1.z, bi1.z), 0.f) * m;
            v1.w = fmaxf(fmaf(b.w, sc1.w, bi1.w), 0.f) * m;
        }
        o[0] = v0;
        o[1] = v1;
    }
}

// ---------------- launch ----------------
extern "C" void kernel_launch(void* const* d_in, const int* in_sizes, int n_in,
                              void* d_out, int out_size) {
    const float* x         = (const float*)d_in[0];
    const float* W         = (const float*)d_in[1];
    const float* gamma     = (const float*)d_in[2];
    const float* beta      = (const float*)d_in[3];
    const int*   offset    = (const int*)d_in[4];
    const int*   out_index = (const int*)d_in[5];
    const float* mask      = (const float*)d_in[6];
    float*       out       = (float*)d_out;

    int N = in_sizes[4];
    if (N > N_MAX) N = N_MAX;

    cudaFuncSetAttribute(k_conv, cudaFuncAttributeMaxDynamicSharedMemorySize,
                         SMEM_BYTES);

    void* pslotPtr = nullptr;
    cudaGetSymbolAddress(&pslotPtr, g_pslot);
    void* cntPtr = nullptr;
    cudaGetSymbolAddress(&cntPtr, g_cntSite);

    cudaMemsetAsync(pslotPtr, 0xFF, sizeof(int) * (size_t)N_MAX * TAPS);   // launch 0
    cudaMemsetAsync(cntPtr, 0, sizeof(int) * (size_t)N_MAX);               // launch 1

    k_prep<<<256, 256>>>(W, offset, N);                                     // 2
    k_prefix<<<1, 32>>>();                                                  // 3
    k_perm<<<256, 256>>>(offset, out_index, mask, N);                       // 4

    int tiles = (N + 127) / 128 + TAPS;   // upper bound incl. per-tap padding
    int tA = tiles / 2, tB = tiles - tA;
    k_conv<<<2 * tA, 256, SMEM_BYTES>>>(x, out, 0);                         // 5  <- ncu -s 5
    k_conv<<<2 * tB, 256, SMEM_BYTES>>>(x, out, tA);                        // 6

    int cb = (N + 511) / 512;
    k_combine<<<cb, 256>>>(out, N);                                         // 7
    k_bn<<<1, 256>>>(gamma, beta);                                          // 8
    k_final<<<cb, 256>>>(out, mask, N);                                     // 9
}